// round 15
// baseline (speedup 1.0000x reference)
#include <cuda_runtime.h>
#include <cuda_bf16.h>

// HashingDiscretizer (R11): R10 smem-pivot design + 8 elems/thread ILP.
//
// calibrated (key in feature table == arange(F)):
//   bin = lower_bound(bin_vals[key*63..+63], val) in [0,63]
//   out_key = (((u32)key * GOLDEN + bin) * GOLDEN) & (2^22-1), out_val = 1
// else: out_key = key & (2^22-1), out_val = val
// Output float[2*nnz] = [out_keys ; out_vals] (exact in f32).
//
// Structure (built per launch by prep kernel; detect block fused in):
//   g_piv[7][F]  pivot SoA {S31 | S15,S47 | S7,S23,S39,S55}  (224KB -> smem)
//   g_row[F][64] sorted rows padded +INF (8 aligned 32B chunks/feature)
// Hot kernel (persistent, 1 block/SM, 1024 thr): per element 3 dependent LDS
// (pivot descent) -> 2x LDG.128 (32B chunk) -> bin. R10 was latency-bound
// (occ 49%, nothing saturated) -> this round batches 8 elements per thread
// with all stream loads issued up front to double in-flight work.

#define NBIN 63
#define MAX_F 8192
#define OUT_MASK 0x3FFFFFu
#define GOLDEN 0x9E3779B9u
#define FEAT_PER_BLOCK 4
#define PIV_FLOATS (7 * MAX_F)
#define SMEM_BYTES (PIV_FLOATS * 4)  // 229376

__device__ float g_piv[PIV_FLOATS];   // [l][f] SoA
__device__ float4 g_row[MAX_F * 16];  // 64 floats per feature, +INF padded
__device__ int g_k64;     // 1 if keys buffer is int64
__device__ int g_f64;     // 1 if feature_ids buffer is int64
__device__ int g_arange;  // 1 if feature_ids == arange(F)

// Fused prep: blocks [0, nb_build) build rows+pivots; block nb_build does
// dtype sniff + arange verification (latency hidden under the build wave).
__global__ __launch_bounds__(256)
void prep_kernel(const float* __restrict__ bin_vals,
                 const unsigned* __restrict__ keys,
                 const unsigned* __restrict__ fid,
                 int nnz, int F, int nb_build) {
    if ((int)blockIdx.x < nb_build) {
        int t = threadIdx.x;
        int f = blockIdx.x * FEAT_PER_BLOCK + (t >> 6);  // 64 threads/feature
        int lane = t & 63;
        if (f >= F) return;
        const float* S = bin_vals + (long long)f * NBIN;
        float* R = reinterpret_cast<float*>(g_row) + (long long)f * 64;
        float inf = __int_as_float(0x7f800000);
        R[lane] = (lane < NBIN) ? S[lane] : inf;  // padded sorted row
        if (lane == 0) {
            g_piv[0 * MAX_F + f] = S[31];
            g_piv[1 * MAX_F + f] = S[15];
            g_piv[2 * MAX_F + f] = S[47];
            g_piv[3 * MAX_F + f] = S[7];
            g_piv[4 * MAX_F + f] = S[23];
            g_piv[5 * MAX_F + f] = S[39];
            g_piv[6 * MAX_F + f] = S[55];
        }
        return;
    }

    // ---- detection block ----
    __shared__ int s_k32, s_f32, s_bad;
    if (threadIdx.x == 0) { s_k32 = 0; s_f32 = 0; s_bad = 0; }
    __syncthreads();
    // int64 little-endian small nonneg values => odd u32 words all zero.
    int lk = 0, lf = 0;
    int nk = min(nnz, 1024);
    for (int i = threadIdx.x; i < nk; i += blockDim.x)
        if (keys[2 * i + 1] != 0u) lk = 1;
    int nf = min(F, 1024);
    for (int i = threadIdx.x; i < nf; i += blockDim.x)
        if (fid[2 * i + 1] != 0u) lf = 1;
    if (lk) atomicOr(&s_k32, 1);
    if (lf) atomicOr(&s_f32, 1);
    __syncthreads();
    int f64 = !s_f32;
    int bad = 0;
    if (f64) {
        const long long* p = (const long long*)fid;
        for (int i = threadIdx.x; i < F; i += blockDim.x)
            if (p[i] != (long long)i) bad = 1;
    } else {
        const int* p = (const int*)fid;
        for (int i = threadIdx.x; i < F; i += blockDim.x)
            if (p[i] != i) bad = 1;
    }
    if (bad) atomicOr(&s_bad, 1);
    __syncthreads();
    if (threadIdx.x == 0) {
        g_k64 = !s_k32;
        g_f64 = f64;
        g_arange = !s_bad;
    }
}

// Calibrated descent: 3 pivot levels from smem, 32B chunk from gmem (L2).
__device__ __forceinline__ void descend(const float* __restrict__ s_piv,
                                        unsigned fx, float v, unsigned key32,
                                        unsigned& okey, float& oval) {
    float p0 = s_piv[fx];                                   // S31
    int b0 = p0 < v;
    float p1 = s_piv[(1 + b0) * MAX_F + fx];                // S15 / S47
    int b1 = p1 < v;
    float p2 = s_piv[(3 + ((b0 << 1) | b1)) * MAX_F + fx];  // S7/S23/S39/S55
    int b2 = p2 < v;
    int p = (b0 << 2) | (b1 << 1) | b2;
    const float4* rp = g_row + fx * 16 + 2 * p;
    float4 c0 = __ldg(rp);
    float4 c1 = __ldg(rp + 1);
    int bin = (p << 3)
            + (c0.x < v) + (c0.y < v) + (c0.z < v) + (c0.w < v)
            + (c1.x < v) + (c1.y < v) + (c1.z < v) + (c1.w < v);
    unsigned h = (key32 * GOLDEN + (unsigned)bin) * GOLDEN;
    okey = h & OUT_MASK;
    oval = 1.0f;
}

// Generic: searchsorted(feature_ids, key, 'left') in gmem, then smem descent.
__device__ __forceinline__ void process_generic(const float* __restrict__ s_piv,
                                                long long key, float v,
                                                const void* fid_, int F,
                                                unsigned& okey, float& oval) {
    int lo = 0, hi = F, fx;
    bool cal;
    if (g_f64) {
        const long long* fid = (const long long*)fid_;
        while (lo < hi) {
            int mid = (lo + hi) >> 1;
            if (__ldg(fid + mid) < key) lo = mid + 1; else hi = mid;
        }
        fx = min(lo, F - 1);
        cal = (__ldg(fid + fx) == key);
    } else {
        const int* fid = (const int*)fid_;
        int k32 = (int)key;
        while (lo < hi) {
            int mid = (lo + hi) >> 1;
            if (__ldg(fid + mid) < k32) lo = mid + 1; else hi = mid;
        }
        fx = min(lo, F - 1);
        cal = (__ldg(fid + fx) == k32);
    }
    if (cal) descend(s_piv, (unsigned)fx, v,
                     (unsigned)(unsigned long long)key, okey, oval);
    else {
        okey = (unsigned)(unsigned long long)key & OUT_MASK;
        oval = v;
    }
}

// Persistent hot kernel: 1 block/SM (224KB smem), grid-stride, 8 elems/iter.
__global__ __launch_bounds__(1024, 1)
void hot_kernel(const void* __restrict__ keys_,
                const float* __restrict__ vals,
                const void* __restrict__ fid_,
                float* __restrict__ out,
                int nnz, int F) {
    extern __shared__ float s_piv[];
    for (int i = threadIdx.x; i < PIV_FLOATS; i += blockDim.x)
        s_piv[i] = __ldg(&g_piv[i]);
    __syncthreads();

    int k64 = g_k64;
    int tid = blockIdx.x * blockDim.x + threadIdx.x;
    int nthreads = gridDim.x * blockDim.x;

    if (!g_arange) {
        // Generic fallback (never taken in practice): scalar grid-stride.
        for (int i = tid; i < nnz; i += nthreads) {
            long long key = k64 ? ((const long long*)keys_)[i]
                                : (long long)((const int*)keys_)[i];
            unsigned ok; float ov;
            process_generic(s_piv, key, vals[i], fid_, F, ok, ov);
            out[i] = (float)ok;
            out[nnz + i] = ov;
        }
        return;
    }

    unsigned uF = (unsigned)F;
    int nvec = nnz >> 3;  // groups of 8

    for (int t = tid; t < nvec; t += nthreads) {
        int base = t * 8;
        unsigned kk[8];
        int cal[8];
        float v[8];

        // --- batch all stream loads up front (max MLP) ---
        if (k64) {
            const longlong2* kp = (const longlong2*)keys_ + t * 4;
#pragma unroll
            for (int j = 0; j < 4; j++) {
                longlong2 a = __ldcs(kp + j);
                kk[2 * j]     = (unsigned)(unsigned long long)a.x;
                cal[2 * j]    = (unsigned long long)a.x < (unsigned long long)F;
                kk[2 * j + 1] = (unsigned)(unsigned long long)a.y;
                cal[2 * j + 1] = (unsigned long long)a.y < (unsigned long long)F;
            }
        } else {
            const int4* kp = (const int4*)keys_ + t * 2;
#pragma unroll
            for (int j = 0; j < 2; j++) {
                int4 a = __ldcs(kp + j);
                kk[4 * j]     = (unsigned)a.x; cal[4 * j]     = (unsigned)a.x < uF;
                kk[4 * j + 1] = (unsigned)a.y; cal[4 * j + 1] = (unsigned)a.y < uF;
                kk[4 * j + 2] = (unsigned)a.z; cal[4 * j + 2] = (unsigned)a.z < uF;
                kk[4 * j + 3] = (unsigned)a.w; cal[4 * j + 3] = (unsigned)a.w < uF;
            }
        }
        const float4* vp = (const float4*)vals + t * 2;
        float4 v0 = __ldcs(vp), v1 = __ldcs(vp + 1);
        v[0] = v0.x; v[1] = v0.y; v[2] = v0.z; v[3] = v0.w;
        v[4] = v1.x; v[5] = v1.y; v[6] = v1.z; v[7] = v1.w;

        // --- 8 independent descents ---
        unsigned ok[8]; float ov[8];
#pragma unroll
        for (int j = 0; j < 8; j++) {
            if (cal[j]) {
                descend(s_piv, kk[j], v[j], kk[j], ok[j], ov[j]);
            } else {
                ok[j] = kk[j] & OUT_MASK;
                ov[j] = v[j];
            }
        }

        // --- batched stores ---
        float4* ko = (float4*)(out + base);
        __stcs(ko, make_float4((float)ok[0], (float)ok[1],
                               (float)ok[2], (float)ok[3]));
        __stcs(ko + 1, make_float4((float)ok[4], (float)ok[5],
                                   (float)ok[6], (float)ok[7]));
        float4* vo = (float4*)(out + nnz + base);
        __stcs(vo, make_float4(ov[0], ov[1], ov[2], ov[3]));
        __stcs(vo + 1, make_float4(ov[4], ov[5], ov[6], ov[7]));
    }

    // tail (nnz not divisible by 8)
    int tail_base = nvec * 8;
    for (int i = tail_base + tid; i < nnz; i += nthreads) {
        long long key = k64 ? ((const long long*)keys_)[i]
                            : (long long)((const int*)keys_)[i];
        float vj = vals[i];
        unsigned ok; float ov;
        if ((unsigned long long)key < (unsigned long long)F)
            descend(s_piv, (unsigned)key, vj,
                    (unsigned)(unsigned long long)key, ok, ov);
        else { ok = (unsigned)(unsigned long long)key & OUT_MASK; ov = vj; }
        out[i] = (float)ok;
        out[nnz + i] = ov;
    }
}

extern "C" void kernel_launch(void* const* d_in, const int* in_sizes, int n_in,
                              void* d_out, int out_size) {
    const void* keys  = d_in[0];
    const float* vals = (const float*)d_in[1];
    const void* fid   = d_in[2];
    const float* bins = (const float*)d_in[3];
    int nnz = in_sizes[0];
    int F   = in_sizes[2];

    int nb_build = (F + FEAT_PER_BLOCK - 1) / FEAT_PER_BLOCK;  // 2048
    prep_kernel<<<nb_build + 1, 256>>>(bins, (const unsigned*)keys,
                                       (const unsigned*)fid, nnz, F, nb_build);

    static int nsm = 0;
    if (nsm == 0) {
        cudaDeviceGetAttribute(&nsm, cudaDevAttrMultiProcessorCount, 0);
        if (nsm <= 0) nsm = 148;
        cudaFuncSetAttribute(hot_kernel,
                             cudaFuncAttributeMaxDynamicSharedMemorySize,
                             SMEM_BYTES);
    }
    hot_kernel<<<nsm, 1024, SMEM_BYTES>>>(keys, vals, fid, (float*)d_out,
                                          nnz, F);
}